// round 13
// baseline (speedup 1.0000x reference)
#include <cuda_runtime.h>

// ---------------------------------------------------------------------------
// GIN via linearize-before-aggregate + fixed-slot CSR gather (no float atomics)
//   y = x@W1;  w = MLP(y[n] + gather(y))@W3;  out = log_softmax(w[n]+gather(w)+b3)
// 4 launches: k0_init, kM(proj+build, smem-staged x), kF1, kF2.
// Gathers: 8 threads/node = 4 float4 columns x 2 list-halves (alternate
// 8-blocks, stride 16). Same total LDG count as R5; 2x warps for latency hiding.
// ---------------------------------------------------------------------------

#define N_NODES_MAX 50000
#define SLOTS 128            // max in-degree bound (true max ~45 for E/N=16 Poisson)

__device__ __align__(16) float g_y  [N_NODES_MAX * 16];
__device__ __align__(16) float g_w  [N_NODES_MAX * 12];
__device__ __align__(16) int   g_csr[N_NODES_MAX * SLOTS];
__device__ int g_cnt[N_NODES_MAX];
__device__ int g_idx64;

__device__ __forceinline__ void f4add(float4& a, float4 b) {
    a.x += b.x; a.y += b.y; a.z += b.z; a.w += b.w;
}

// ---------------------------------------------------------------------------
// k0: zero per-node counts; block 0 probes edge dtype (int64 -> odd words 0)
// ---------------------------------------------------------------------------
__global__ void k0_init(const int* __restrict__ ei_words, int N) {
    int gid = blockIdx.x * blockDim.x + threadIdx.x;
    if (gid < N) g_cnt[gid] = 0;
    if (blockIdx.x == 0 && threadIdx.x < 32) {
        int t = threadIdx.x;
        int v = ei_words[2 * t + 1] | ei_words[64 + 2 * t + 1];
        unsigned any = __ballot_sync(0xffffffffu, v != 0);
        if (t == 0) g_idx64 = (any == 0u) ? 1 : 0;
    }
}

// ---------------------------------------------------------------------------
// kM: merged grid. First N*16 threads: y = x@W1 (16 thr/node, x staged in
// smem: each row loaded from global ONCE, then broadcast-read). Remaining E
// threads: CSR build. N*16 % 256 == 0 -> proj/edge blocks never straddle.
// ---------------------------------------------------------------------------
__global__ void kM_proj_build(const float* __restrict__ x,
                              const float* __restrict__ W1,
                              const void* __restrict__ ei, int N, int E) {
    __shared__ float sW[64 * 16];
    __shared__ float4 sX[16 * 16];   // 16 nodes x 16 float4 (64 floats)
    int PROJ = N * 16;
    int gid = blockIdx.x * blockDim.x + threadIdx.x;
    bool projBlock = (blockIdx.x * blockDim.x) < (unsigned)PROJ;
    if (projBlock) {
        for (int i = threadIdx.x; i < 64 * 16; i += blockDim.x) sW[i] = W1[i];
        int nodeBase = (blockIdx.x * blockDim.x) >> 4;   // first node of block
        int rows = min(16, N - nodeBase);
        const float4* xg = (const float4*)x + nodeBase * 16;
        if (threadIdx.x < rows * 16) sX[threadIdx.x] = xg[threadIdx.x];
        __syncthreads();
    }
    if (gid < PROJ) {
        int j  = gid & 15;
        int ln = (threadIdx.x >> 4);          // node index within block
        const float4* xr = sX + ln * 16;
        float acc = 0.0f;
        #pragma unroll
        for (int q = 0; q < 16; q++) {
            float4 xv = xr[q];
            int k = 4 * q;
            acc += xv.x * sW[(k + 0) * 16 + j];
            acc += xv.y * sW[(k + 1) * 16 + j];
            acc += xv.z * sW[(k + 2) * 16 + j];
            acc += xv.w * sW[(k + 3) * 16 + j];
        }
        g_y[gid] = acc;
    } else {
        int e = gid - PROJ;
        if (e < E) {
            int src, dst;
            if (g_idx64) {
                const long long* p = (const long long*)ei;
                src = (int)p[e];
                dst = (int)p[E + e];
            } else {
                const int* p = (const int*)ei;
                src = p[e];
                dst = p[E + e];
            }
            int rank = atomicAdd(&g_cnt[dst], 1);
            if (rank < SLOTS) g_csr[dst * SLOTS + rank] = src;
        }
    }
}

// ---------------------------------------------------------------------------
// Half-list gather: thread (c, h) sums float4 column c over alternate 8-blocks
// of node n's list (blocks h, h+2, ...). Remainder (<8) goes to half nb&1.
// Self term added by h==0. Caller merges halves with shfl_xor(...,4,8).
// ---------------------------------------------------------------------------
__device__ __forceinline__ float4 gather_half(const float4* __restrict__ row4,
                                              int n, int c, int h, int stride) {
    float4 acc = (h == 0) ? row4[n * stride + c]
                          : make_float4(0.0f, 0.0f, 0.0f, 0.0f);
    int cnt = min(g_cnt[n], SLOTS);
    const int* lst = g_csr + n * SLOTS;
    int nb = cnt >> 3;                         // full 8-blocks
    for (int b = h; b < nb; b += 2) {
        const int* p = lst + b * 8;
        int4 s0 = *(const int4*)(p);
        int4 s1 = *(const int4*)(p + 4);
        float4 a0 = row4[s0.x * stride + c];
        float4 a1 = row4[s0.y * stride + c];
        float4 a2 = row4[s0.z * stride + c];
        float4 a3 = row4[s0.w * stride + c];
        float4 a4 = row4[s1.x * stride + c];
        float4 a5 = row4[s1.y * stride + c];
        float4 a6 = row4[s1.z * stride + c];
        float4 a7 = row4[s1.w * stride + c];
        f4add(acc, a0); f4add(acc, a1); f4add(acc, a2); f4add(acc, a3);
        f4add(acc, a4); f4add(acc, a5); f4add(acc, a6); f4add(acc, a7);
    }
    if (h == (nb & 1)) {                       // remainder to next half in RR
        int r = nb * 8;
        if (r + 4 <= cnt) {                    // 8-aligned -> int4 OK
            int4 s = *(const int4*)(lst + r);
            float4 a0 = row4[s.x * stride + c];
            float4 a1 = row4[s.y * stride + c];
            float4 a2 = row4[s.z * stride + c];
            float4 a3 = row4[s.w * stride + c];
            f4add(acc, a0); f4add(acc, a1); f4add(acc, a2); f4add(acc, a3);
            r += 4;
        }
        for (; r < cnt; r++) f4add(acc, row4[lst[r] * stride + c]);
    }
    return acc;
}

// ---------------------------------------------------------------------------
// kF1: fused gather(16) + MLP + W3 projection. 8 threads/node:
// c = lane&3 (float4 column), h = (lane>>2)&1 (list half). After the halves
// merge (shfl_xor 4), both halves run the MLP redundantly (fma is cheap);
// h==0 stores. Width-4 butterflies operate within each aligned half-group.
// ---------------------------------------------------------------------------
__global__ void kF1_gather_mlp(const float* __restrict__ b1, const float* __restrict__ W2,
                               const float* __restrict__ b2, const float* __restrict__ gamma,
                               const float* __restrict__ beta, const float* __restrict__ mean,
                               const float* __restrict__ var, const float* __restrict__ W3,
                               int N) {
    __shared__ float sS[16], sB1[16], sB2[16], sW2[16 * 17], sW3[16 * 11];
    int tid = threadIdx.x;
    if (tid < 16) {
        float s = gamma[tid] * rsqrtf(var[tid] + 1e-5f);
        sS[tid]  = s;
        sB1[tid] = b1[tid];
        sB2[tid] = (b2[tid] - mean[tid]) * s + beta[tid];
    }
    __syncthreads();
    for (int i = tid; i < 256; i += blockDim.x) {
        int k = i >> 4, j = i & 15;
        sW2[k * 17 + j] = W2[i] * sS[j];
    }
    for (int i = tid; i < 160; i += blockDim.x) {
        int k = i / 10, j = i - 10 * k;
        sW3[k * 11 + j] = W3[i];
    }
    __syncthreads();

    int gid = blockIdx.x * blockDim.x + tid;
    int n = gid >> 3;
    int c = gid & 3;
    int h = (gid >> 2) & 1;
    bool valid = (n < N);
    int ncl = valid ? n : (N - 1);

    float4 acc = gather_half((const float4*)g_y, ncl, c, h, 4);
    // merge halves: lanes (c,0) and (c,1) both end with the full sum
    acc.x += __shfl_xor_sync(0xffffffffu, acc.x, 4, 8);
    acc.y += __shfl_xor_sync(0xffffffffu, acc.y, 4, 8);
    acc.z += __shfl_xor_sync(0xffffffffu, acc.z, 4, 8);
    acc.w += __shfl_xor_sync(0xffffffffu, acc.w, 4, 8);

    // ---- MLP (both halves compute; h==0 stores) ----
    int kb = 4 * c;
    float h0 = fmaxf(acc.x + sB1[kb + 0], 0.0f);
    float h1 = fmaxf(acc.y + sB1[kb + 1], 0.0f);
    float h2 = fmaxf(acc.z + sB1[kb + 2], 0.0f);
    float h3 = fmaxf(acc.w + sB1[kb + 3], 0.0f);

    float t[16];
    #pragma unroll
    for (int j = 0; j < 16; j++) {
        t[j] = h0 * sW2[(kb + 0) * 17 + j]
             + h1 * sW2[(kb + 1) * 17 + j]
             + h2 * sW2[(kb + 2) * 17 + j]
             + h3 * sW2[(kb + 3) * 17 + j];
    }
    #pragma unroll
    for (int j = 0; j < 16; j++) {
        t[j] += __shfl_xor_sync(0xffffffffu, t[j], 1, 4);
        t[j] += __shfl_xor_sync(0xffffffffu, t[j], 2, 4);
        t[j] = fmaxf(t[j] + sB2[j], 0.0f);
    }

    float w[10];
    #pragma unroll
    for (int j = 0; j < 10; j++) {
        w[j] = t[kb + 0] * sW3[(kb + 0) * 11 + j]
             + t[kb + 1] * sW3[(kb + 1) * 11 + j]
             + t[kb + 2] * sW3[(kb + 2) * 11 + j]
             + t[kb + 3] * sW3[(kb + 3) * 11 + j];
        w[j] += __shfl_xor_sync(0xffffffffu, w[j], 1, 4);
        w[j] += __shfl_xor_sync(0xffffffffu, w[j], 2, 4);
    }

    if (valid && h == 0 && c < 3) {
        float4 out;
        if (c == 0)      out = make_float4(w[0], w[1], w[2], w[3]);
        else if (c == 1) out = make_float4(w[4], w[5], w[6], w[7]);
        else             out = make_float4(w[8], w[9], 0.0f, 0.0f);
        ((float4*)g_w)[n * 3 + c] = out;
    }
}

// ---------------------------------------------------------------------------
// kF2: fused gather(12) + log_softmax. 8 threads/node; lanes c<3 gather their
// column half; halves merge; lane (0,0) collects logits, computes lsm, writes.
// ---------------------------------------------------------------------------
__global__ void kF2_gather_lsm(const float* __restrict__ b3,
                               float* __restrict__ out, int N) {
    int gid = blockIdx.x * blockDim.x + threadIdx.x;
    int n = gid >> 3;
    int c = gid & 3;
    int h = (gid >> 2) & 1;
    bool valid = (n < N);
    int ncl = valid ? n : (N - 1);

    float4 acc = make_float4(0.0f, 0.0f, 0.0f, 0.0f);
    if (c < 3) acc = gather_half((const float4*)g_w, ncl, c, h, 3);

    acc.x += __shfl_xor_sync(0xffffffffu, acc.x, 4, 8);
    acc.y += __shfl_xor_sync(0xffffffffu, acc.y, 4, 8);
    acc.z += __shfl_xor_sync(0xffffffffu, acc.z, 4, 8);
    acc.w += __shfl_xor_sync(0xffffffffu, acc.w, 4, 8);

    // collect 10 logits at lane 0 of each 8-lane group
    float v4x = __shfl_sync(0xffffffffu, acc.x, 1, 8);
    float v5  = __shfl_sync(0xffffffffu, acc.y, 1, 8);
    float v6  = __shfl_sync(0xffffffffu, acc.z, 1, 8);
    float v7  = __shfl_sync(0xffffffffu, acc.w, 1, 8);
    float v8  = __shfl_sync(0xffffffffu, acc.x, 2, 8);
    float v9  = __shfl_sync(0xffffffffu, acc.y, 2, 8);

    if (valid && c == 0 && h == 0) {
        float v[10];
        v[0] = acc.x + __ldg(&b3[0]);
        v[1] = acc.y + __ldg(&b3[1]);
        v[2] = acc.z + __ldg(&b3[2]);
        v[3] = acc.w + __ldg(&b3[3]);
        v[4] = v4x   + __ldg(&b3[4]);
        v[5] = v5    + __ldg(&b3[5]);
        v[6] = v6    + __ldg(&b3[6]);
        v[7] = v7    + __ldg(&b3[7]);
        v[8] = v8    + __ldg(&b3[8]);
        v[9] = v9    + __ldg(&b3[9]);

        float m = v[0];
        #pragma unroll
        for (int j = 1; j < 10; j++) m = fmaxf(m, v[j]);
        float s = 0.0f;
        #pragma unroll
        for (int j = 0; j < 10; j++) s += expf(v[j] - m);
        float lse = m + logf(s);

        float2* o2 = (float2*)(out + n * 10);   // 40B rows -> 8B aligned
        #pragma unroll
        for (int q = 0; q < 5; q++)
            o2[q] = make_float2(v[2 * q] - lse, v[2 * q + 1] - lse);
    }
}

// ---------------------------------------------------------------------------
extern "C" void kernel_launch(void* const* d_in, const int* in_sizes, int n_in,
                              void* d_out, int out_size) {
    const float* x     = (const float*)d_in[0];
    const void*  ei    = d_in[1];
    const float* W1    = (const float*)d_in[2];
    const float* b1    = (const float*)d_in[3];
    const float* W2    = (const float*)d_in[4];
    const float* b2    = (const float*)d_in[5];
    const float* gamma = (const float*)d_in[6];
    const float* beta  = (const float*)d_in[7];
    const float* mean  = (const float*)d_in[8];
    const float* var   = (const float*)d_in[9];
    const float* W3    = (const float*)d_in[10];
    const float* b3    = (const float*)d_in[11];

    int N = in_sizes[0] / 64;   // 50000
    int E = in_sizes[1] / 2;    // 800000

    k0_init<<<(N + 255) / 256, 256>>>((const int*)ei, N);
    kM_proj_build<<<(N * 16 + E + 255) / 256, 256>>>(x, W1, ei, N, E);
    kF1_gather_mlp<<<(N * 8 + 255) / 256, 256>>>(b1, W2, b2, gamma, beta, mean, var, W3, N);
    kF2_gather_lsm<<<(N * 8 + 255) / 256, 256>>>(b3, (float*)d_out, N);
}

// round 14
// speedup vs baseline: 1.1706x; 1.1706x over previous
#include <cuda_runtime.h>

// ---------------------------------------------------------------------------
// GIN via linearize-before-aggregate + fixed-slot CSR gather (no float atomics)
//   y = x@W1;  w = MLP(y[n] + gather(y))@W3;  out = log_softmax(w[n]+gather(w)+b3)
// 4 launches: k0(1-block dtype probe), kM(proj+build, smem-staged x),
//   kF1(gather16+MLP), kF2(gather12+lsm, restores g_cnt=0 for next call).
// g_cnt zero invariant: zero-initialized at load; kF2 lane c==3 re-zeros it
// after the warp's last read (shfl_sync converges the warp first).
// Gathers are R5/R12-exact (proven optimum: 4 thr/node, float4, unroll-8).
// ---------------------------------------------------------------------------

#define N_NODES_MAX 50000
#define SLOTS 128            // max in-degree bound (true max ~45 for E/N=16 Poisson)

__device__ __align__(16) float g_y  [N_NODES_MAX * 16];
__device__ __align__(16) float g_w  [N_NODES_MAX * 12];
__device__ __align__(16) int   g_csr[N_NODES_MAX * SLOTS];
__device__ int g_cnt[N_NODES_MAX];   // zero-init; kF2 restores zeros each call
__device__ int g_idx64;

__device__ __forceinline__ void f4add(float4& a, float4 b) {
    a.x += b.x; a.y += b.y; a.z += b.z; a.w += b.w;
}

// ---------------------------------------------------------------------------
// k0: single-warp edge dtype probe (int64 -> odd 32-bit words all zero)
// ---------------------------------------------------------------------------
__global__ void k0_probe(const int* __restrict__ ei_words) {
    int t = threadIdx.x;
    int v = ei_words[2 * t + 1] | ei_words[64 + 2 * t + 1];
    unsigned any = __ballot_sync(0xffffffffu, v != 0);
    if (t == 0) g_idx64 = (any == 0u) ? 1 : 0;
}

// ---------------------------------------------------------------------------
// kM: merged grid. First N*16 threads: y = x@W1 (16 thr/node, x staged in
// smem: each row loaded from global ONCE, then broadcast-read). Remaining E
// threads: CSR build. N*16 % 256 == 0 -> proj/edge blocks never straddle.
// ---------------------------------------------------------------------------
__global__ void kM_proj_build(const float* __restrict__ x,
                              const float* __restrict__ W1,
                              const void* __restrict__ ei, int N, int E) {
    __shared__ float sW[64 * 16];
    __shared__ float4 sX[16 * 16];   // 16 nodes x 16 float4 (64 floats)
    int PROJ = N * 16;
    int gid = blockIdx.x * blockDim.x + threadIdx.x;
    bool projBlock = (blockIdx.x * blockDim.x) < (unsigned)PROJ;
    if (projBlock) {
        for (int i = threadIdx.x; i < 64 * 16; i += blockDim.x) sW[i] = W1[i];
        int nodeBase = (blockIdx.x * blockDim.x) >> 4;   // first node of block
        int rows = min(16, N - nodeBase);
        const float4* xg = (const float4*)x + nodeBase * 16;
        if (threadIdx.x < rows * 16) sX[threadIdx.x] = xg[threadIdx.x];
        __syncthreads();
    }
    if (gid < PROJ) {
        int j  = gid & 15;
        int ln = (threadIdx.x >> 4);          // node index within block
        const float4* xr = sX + ln * 16;
        float acc = 0.0f;
        #pragma unroll
        for (int q = 0; q < 16; q++) {
            float4 xv = xr[q];
            int k = 4 * q;
            acc += xv.x * sW[(k + 0) * 16 + j];
            acc += xv.y * sW[(k + 1) * 16 + j];
            acc += xv.z * sW[(k + 2) * 16 + j];
            acc += xv.w * sW[(k + 3) * 16 + j];
        }
        g_y[gid] = acc;
    } else {
        int e = gid - PROJ;
        if (e < E) {
            int src, dst;
            if (g_idx64) {
                const long long* p = (const long long*)ei;
                src = (int)p[e];
                dst = (int)p[E + e];
            } else {
                const int* p = (const int*)ei;
                src = p[e];
                dst = p[E + e];
            }
            int rank = atomicAdd(&g_cnt[dst], 1);
            if (rank < SLOTS) g_csr[dst * SLOTS + rank] = src;
        }
    }
}

// ---------------------------------------------------------------------------
// kF1: fused gather(16) + MLP + W3 projection. 4 threads/node, lane c owns
// float4 column c. Neighbor loop unrolled x8 (R5-exact).
// smem strides 17/11 -> lane banks conflict-free for 4-lane groups.
// ---------------------------------------------------------------------------
__global__ void kF1_gather_mlp(const float* __restrict__ b1, const float* __restrict__ W2,
                               const float* __restrict__ b2, const float* __restrict__ gamma,
                               const float* __restrict__ beta, const float* __restrict__ mean,
                               const float* __restrict__ var, const float* __restrict__ W3,
                               int N) {
    __shared__ float sS[16], sB1[16], sB2[16], sW2[16 * 17], sW3[16 * 11];
    int tid = threadIdx.x;
    if (tid < 16) {
        float s = gamma[tid] * rsqrtf(var[tid] + 1e-5f);
        sS[tid]  = s;
        sB1[tid] = b1[tid];
        sB2[tid] = (b2[tid] - mean[tid]) * s + beta[tid];
    }
    __syncthreads();
    for (int i = tid; i < 256; i += blockDim.x) {
        int k = i >> 4, j = i & 15;
        sW2[k * 17 + j] = W2[i] * sS[j];
    }
    for (int i = tid; i < 160; i += blockDim.x) {
        int k = i / 10, j = i - 10 * k;
        sW3[k * 11 + j] = W3[i];
    }
    __syncthreads();

    int gid = blockIdx.x * blockDim.x + tid;
    int n = gid >> 2;
    int c = gid & 3;
    if (n >= N) return;

    const float4* y4 = (const float4*)g_y;
    float4 acc = y4[n * 4 + c];                 // self term
    int cnt = min(g_cnt[n], SLOTS);
    const int* lst = g_csr + n * SLOTS;

    int r = 0;
    for (; r + 8 <= cnt; r += 8) {
        int4 s0 = *(const int4*)(lst + r);
        int4 s1 = *(const int4*)(lst + r + 4);
        float4 a0 = y4[s0.x * 4 + c];
        float4 a1 = y4[s0.y * 4 + c];
        float4 a2 = y4[s0.z * 4 + c];
        float4 a3 = y4[s0.w * 4 + c];
        float4 a4 = y4[s1.x * 4 + c];
        float4 a5 = y4[s1.y * 4 + c];
        float4 a6 = y4[s1.z * 4 + c];
        float4 a7 = y4[s1.w * 4 + c];
        f4add(acc, a0); f4add(acc, a1); f4add(acc, a2); f4add(acc, a3);
        f4add(acc, a4); f4add(acc, a5); f4add(acc, a6); f4add(acc, a7);
    }
    if (r + 4 <= cnt) {
        int4 s = *(const int4*)(lst + r);
        float4 a0 = y4[s.x * 4 + c];
        float4 a1 = y4[s.y * 4 + c];
        float4 a2 = y4[s.z * 4 + c];
        float4 a3 = y4[s.w * 4 + c];
        f4add(acc, a0); f4add(acc, a1); f4add(acc, a2); f4add(acc, a3);
        r += 4;
    }
    for (; r < cnt; r++) f4add(acc, y4[lst[r] * 4 + c]);

    // ---- MLP ----
    int kb = 4 * c;
    float h0 = fmaxf(acc.x + sB1[kb + 0], 0.0f);
    float h1 = fmaxf(acc.y + sB1[kb + 1], 0.0f);
    float h2 = fmaxf(acc.z + sB1[kb + 2], 0.0f);
    float h3 = fmaxf(acc.w + sB1[kb + 3], 0.0f);

    float t[16];
    #pragma unroll
    for (int j = 0; j < 16; j++) {
        t[j] = h0 * sW2[(kb + 0) * 17 + j]
             + h1 * sW2[(kb + 1) * 17 + j]
             + h2 * sW2[(kb + 2) * 17 + j]
             + h3 * sW2[(kb + 3) * 17 + j];
    }
    #pragma unroll
    for (int j = 0; j < 16; j++) {
        t[j] += __shfl_xor_sync(0xffffffffu, t[j], 1, 4);
        t[j] += __shfl_xor_sync(0xffffffffu, t[j], 2, 4);
        t[j] = fmaxf(t[j] + sB2[j], 0.0f);
    }

    float w[10];
    #pragma unroll
    for (int j = 0; j < 10; j++) {
        w[j] = t[kb + 0] * sW3[(kb + 0) * 11 + j]
             + t[kb + 1] * sW3[(kb + 1) * 11 + j]
             + t[kb + 2] * sW3[(kb + 2) * 11 + j]
             + t[kb + 3] * sW3[(kb + 3) * 11 + j];
        w[j] += __shfl_xor_sync(0xffffffffu, w[j], 1, 4);
        w[j] += __shfl_xor_sync(0xffffffffu, w[j], 2, 4);
    }

    if (c < 3) {
        float4 out;
        if (c == 0)      out = make_float4(w[0], w[1], w[2], w[3]);
        else if (c == 1) out = make_float4(w[4], w[5], w[6], w[7]);
        else             out = make_float4(w[8], w[9], 0.0f, 0.0f);
        ((float4*)g_w)[n * 3 + c] = out;
    }
}

// ---------------------------------------------------------------------------
// kF2: fused gather(12) + log_softmax. 4 threads/node; lanes 0-2 gather their
// float4 column (unroll x8); lane 0 collects via shuffles, computes lsm,
// writes. Lane 3 (idle in gather) restores g_cnt[n]=0 AFTER the shuffles
// (shfl_sync converges the warp, so all g_cnt reads have completed).
// ---------------------------------------------------------------------------
__global__ void kF2_gather_lsm(const float* __restrict__ b3,
                               float* __restrict__ out, int N) {
    int gid = blockIdx.x * blockDim.x + threadIdx.x;
    int n = gid >> 2;
    int c = gid & 3;
    if (n >= N) return;

    const float4* w4 = (const float4*)g_w;
    float4 acc = make_float4(0.0f, 0.0f, 0.0f, 0.0f);
    int cnt = min(g_cnt[n], SLOTS);
    const int* lst = g_csr + n * SLOTS;

    if (c < 3) {
        acc = w4[n * 3 + c];                    // self term
        int r = 0;
        for (; r + 8 <= cnt; r += 8) {
            int4 s0 = *(const int4*)(lst + r);
            int4 s1 = *(const int4*)(lst + r + 4);
            float4 a0 = w4[s0.x * 3 + c];
            float4 a1 = w4[s0.y * 3 + c];
            float4 a2 = w4[s0.z * 3 + c];
            float4 a3 = w4[s0.w * 3 + c];
            float4 a4 = w4[s1.x * 3 + c];
            float4 a5 = w4[s1.y * 3 + c];
            float4 a6 = w4[s1.z * 3 + c];
            float4 a7 = w4[s1.w * 3 + c];
            f4add(acc, a0); f4add(acc, a1); f4add(acc, a2); f4add(acc, a3);
            f4add(acc, a4); f4add(acc, a5); f4add(acc, a6); f4add(acc, a7);
        }
        if (r + 4 <= cnt) {
            int4 s = *(const int4*)(lst + r);
            float4 a0 = w4[s.x * 3 + c];
            float4 a1 = w4[s.y * 3 + c];
            float4 a2 = w4[s.z * 3 + c];
            float4 a3 = w4[s.w * 3 + c];
            f4add(acc, a0); f4add(acc, a1); f4add(acc, a2); f4add(acc, a3);
            r += 4;
        }
        for (; r < cnt; r++) f4add(acc, w4[lst[r] * 3 + c]);
    }

    // collect 10 logits at lane 0 of each 4-lane group (also converges warp)
    float v4x = __shfl_sync(0xffffffffu, acc.x, 1, 4);
    float v5  = __shfl_sync(0xffffffffu, acc.y, 1, 4);
    float v6  = __shfl_sync(0xffffffffu, acc.z, 1, 4);
    float v7  = __shfl_sync(0xffffffffu, acc.w, 1, 4);
    float v8  = __shfl_sync(0xffffffffu, acc.x, 2, 4);
    float v9  = __shfl_sync(0xffffffffu, acc.y, 2, 4);

    if (c == 3) g_cnt[n] = 0;   // restore zero invariant for the next call

    if (c == 0) {
        float v[10];
        v[0] = acc.x + __ldg(&b3[0]);
        v[1] = acc.y + __ldg(&b3[1]);
        v[2] = acc.z + __ldg(&b3[2]);
        v[3] = acc.w + __ldg(&b3[3]);
        v[4] = v4x   + __ldg(&b3[4]);
        v[5] = v5    + __ldg(&b3[5]);
        v[6] = v6    + __ldg(&b3[6]);
        v[7] = v7    + __ldg(&b3[7]);
        v[8] = v8    + __ldg(&b3[8]);
        v[9] = v9    + __ldg(&b3[9]);

        float m = v[0];
        #pragma unroll
        for (int j = 1; j < 10; j++) m = fmaxf(m, v[j]);
        float s = 0.0f;
        #pragma unroll
        for (int j = 0; j < 10; j++) s += expf(v[j] - m);
        float lse = m + logf(s);

        float2* o2 = (float2*)(out + n * 10);   // 40B rows -> 8B aligned
        #pragma unroll
        for (int q = 0; q < 5; q++)
            o2[q] = make_float2(v[2 * q] - lse, v[2 * q + 1] - lse);
    }
}

// ---------------------------------------------------------------------------
extern "C" void kernel_launch(void* const* d_in, const int* in_sizes, int n_in,
                              void* d_out, int out_size) {
    const float* x     = (const float*)d_in[0];
    const void*  ei    = d_in[1];
    const float* W1    = (const float*)d_in[2];
    const float* b1    = (const float*)d_in[3];
    const float* W2    = (const float*)d_in[4];
    const float* b2    = (const float*)d_in[5];
    const float* gamma = (const float*)d_in[6];
    const float* beta  = (const float*)d_in[7];
    const float* mean  = (const float*)d_in[8];
    const float* var   = (const float*)d_in[9];
    const float* W3    = (const float*)d_in[10];
    const float* b3    = (const float*)d_in[11];

    int N = in_sizes[0] / 64;   // 50000
    int E = in_sizes[1] / 2;    // 800000

    k0_probe<<<1, 32>>>((const int*)ei);
    kM_proj_build<<<(N * 16 + E + 255) / 256, 256>>>(x, W1, ei, N, E);
    kF1_gather_mlp<<<(N * 4 + 255) / 256, 256>>>(b1, W2, b2, gamma, beta, mean, var, W3, N);
    kF2_gather_lsm<<<(N * 4 + 255) / 256, 256>>>(b3, (float*)d_out, N);
}